// round 7
// baseline (speedup 1.0000x reference)
#include <cuda_runtime.h>
#include <math.h>

// Problem shape (fixed by the dataset instance)
#define BATCH 16
#define HEADS 8
#define HDIM  128
#define BSIZE 16               // tokens per cache block
#define BPS   128              // blocks per sequence
#define TMAX  (BSIZE * BPS)    // 2048 tokens
#define NSPLIT 4
#define TSPLIT (TMAX / NSPLIT)     // 512 tokens per split
#define BLKSPLIT (TSPLIT / BSIZE)  // 32 cache blocks per split
#define THREADS 256
#define NWARPS  (THREADS / 32)     // 8
#define TPW     (TSPLIT / NWARPS)  // 64 tokens per warp

// split-KV partials + completion counters (allocation-free scratch, zero-init)
__device__ float g_part_o[BATCH * HEADS * NSPLIT * HDIM];
__device__ float g_part_m[BATCH * HEADS * NSPLIT];
__device__ float g_part_l[BATCH * HEADS * NSPLIT];
__device__ unsigned int g_cnt[BATCH * HEADS];

__device__ __forceinline__ float warp_sum(float v) {
#pragma unroll
    for (int o = 16; o > 0; o >>= 1) v += __shfl_xor_sync(0xffffffffu, v, o);
    return v;
}

__global__ __launch_bounds__(THREADS)
void paged_attn_split_kernel(const float* __restrict__ q,
                             const float* __restrict__ knew,
                             const float* __restrict__ vnew,
                             const float* __restrict__ kcache,
                             const float* __restrict__ vcache,
                             const int*   __restrict__ block_tables,
                             const int*   __restrict__ context_lens,
                             float*       __restrict__ out)
{
    const float SCALE = 0.08838834764831845f;

    // Grid layout: adjacent CTAs = the 8 heads of the same (b, split) chunk.
    const int idx   = blockIdx.x;
    const int h     = idx % HEADS;
    const int bs_   = idx / HEADS;
    const int split = bs_ % NSPLIT;
    const int b     = bs_ / NSPLIT;
    const int bh    = b * HEADS + h;

    const int tid   = threadIdx.x;
    const int lane  = tid & 31;
    const int w     = tid >> 5;
    const int tbase = split * TSPLIT;

    __shared__ float s_scores[TSPLIT];
    __shared__ int   s_bt[BLKSPLIT];
    __shared__ float s_m[NWARPS];
    __shared__ float s_l[NWARPS];
    __shared__ float s_acc[NWARPS][HDIM];
    __shared__ unsigned int s_last;

    if (tid < BLKSPLIT)
        s_bt[tid] = block_tables[b * BPS + split * BLKSPLIT + tid];

    const int ctx  = context_lens[b];
    const int last = ctx - 1;

    float4 q4 = reinterpret_cast<const float4*>(q + (size_t)bh * HDIM)[lane];
    q4.x *= SCALE; q4.y *= SCALE; q4.z *= SCALE; q4.w *= SCALE;

    const float* kfresh = knew + (size_t)bh * HDIM;
    const float* vfresh = vnew + (size_t)bh * HDIM;

    __syncthreads();

    const int lbeg = w * TPW;
    const int lend = lbeg + TPW;

    // helper macro: load 4 consecutive tokens' rows of a cache into buf
#define LOAD4(buf, base_lt, cache, fresh)                                          \
    {                                                                              \
        _Pragma("unroll")                                                          \
        for (int i = 0; i < 4; i++) {                                              \
            const int lt = (base_lt) + i;                                          \
            const int t  = tbase + lt;                                             \
            const int blk = s_bt[lt >> 4];                                         \
            const size_t row = ((size_t)blk * BSIZE + (t & (BSIZE - 1))) * HEADS + h; \
            const float* ptr = (t == last) ? (fresh) : ((cache) + row * HDIM);     \
            buf[i] = reinterpret_cast<const float4*>(ptr)[lane];                   \
        }                                                                          \
    }

    // ---------------- Phase 1: scores, software-pipelined -------------------
    float m = -INFINITY;                    // per-warp max (warp-uniform)
    {
        float4 kvA[4], kvB[4];
        LOAD4(kvA, lbeg, kcache, kfresh);   // prologue

#pragma unroll 1
        for (int l0 = lbeg; l0 < lend; l0 += 8) {
            // prefetch second half while reducing first half
            LOAD4(kvB, l0 + 4, kcache, kfresh);
#pragma unroll
            for (int i = 0; i < 4; i++) {
                float s = kvA[i].x * q4.x + kvA[i].y * q4.y
                        + kvA[i].z * q4.z + kvA[i].w * q4.w;
                s = warp_sum(s);
                const int lt = l0 + i;
                const float sv = (tbase + lt < ctx) ? s : -INFINITY;
                m = fmaxf(m, sv);
                if (lane == i) s_scores[lt] = sv;
            }
            // prefetch next iteration's first half while reducing second half
            if (l0 + 8 < lend) LOAD4(kvA, l0 + 8, kcache, kfresh);
#pragma unroll
            for (int i = 0; i < 4; i++) {
                float s = kvB[i].x * q4.x + kvB[i].y * q4.y
                        + kvB[i].z * q4.z + kvB[i].w * q4.w;
                s = warp_sum(s);
                const int lt = l0 + 4 + i;
                const float sv = (tbase + lt < ctx) ? s : -INFINITY;
                m = fmaxf(m, sv);
                if (lane == i) s_scores[lt] = sv;
            }
        }
    }
    __syncwarp();

    // ---------------- Phase 2: per-warp softmax ------------------------------
    const float msafe = (m == -INFINITY) ? 0.0f : m;
    float e0 = __expf(s_scores[lbeg + lane]      - msafe);
    float e1 = __expf(s_scores[lbeg + 32 + lane] - msafe);
    s_scores[lbeg + lane]      = e0;
    s_scores[lbeg + 32 + lane] = e1;
    const float l = warp_sum(e0 + e1);
    __syncwarp();

    // ---------------- Phase 3: o = sum p_t v_t, software-pipelined ----------
    float4 acc = make_float4(0.f, 0.f, 0.f, 0.f);
    {
        float4 vvA[4], vvB[4];
        LOAD4(vvA, lbeg, vcache, vfresh);   // prologue

#pragma unroll 1
        for (int l0 = lbeg; l0 < lend; l0 += 8) {
            LOAD4(vvB, l0 + 4, vcache, vfresh);
#pragma unroll
            for (int i = 0; i < 4; i++) {
                const float p = s_scores[l0 + i];        // LDS broadcast
                acc.x += p * vvA[i].x;
                acc.y += p * vvA[i].y;
                acc.z += p * vvA[i].z;
                acc.w += p * vvA[i].w;
            }
            if (l0 + 8 < lend) LOAD4(vvA, l0 + 8, vcache, vfresh);
#pragma unroll
            for (int i = 0; i < 4; i++) {
                const float p = s_scores[l0 + 4 + i];
                acc.x += p * vvB[i].x;
                acc.y += p * vvB[i].y;
                acc.z += p * vvB[i].z;
                acc.w += p * vvB[i].w;
            }
        }
    }
#undef LOAD4

    // ------------- cross-warp merge -> split partial ------------------------
    if (lane == 0) { s_m[w] = m; s_l[w] = l; }
    reinterpret_cast<float4*>(s_acc[w])[lane] = acc;
    __syncthreads();

    float M = -INFINITY;
#pragma unroll
    for (int ww = 0; ww < NWARPS; ww++) M = fmaxf(M, s_m[ww]);

    const int ps = bh * NSPLIT + split;
    if (tid < HDIM) {
        float r = 0.f;
#pragma unroll
        for (int ww = 0; ww < NWARPS; ww++) {
            const float coef = (s_m[ww] == -INFINITY) ? 0.f : __expf(s_m[ww] - M);
            r += coef * s_acc[ww][tid];
        }
        g_part_o[(size_t)ps * HDIM + tid] = r;
    }
    if (tid == 0) {
        float L = 0.f;
#pragma unroll
        for (int ww = 0; ww < NWARPS; ww++) {
            const float coef = (s_m[ww] == -INFINITY) ? 0.f : __expf(s_m[ww] - M);
            L += coef * s_l[ww];
        }
        g_part_m[ps] = M;
        g_part_l[ps] = L;
    }

    // ------------- last CTA per (b,h) combines (fused, no 2nd launch) ------
    __threadfence();
    __syncthreads();
    if (tid == 0)
        s_last = atomicAdd(&g_cnt[bh], 1u);
    __syncthreads();
    if (s_last != NSPLIT - 1) return;
    __threadfence();

    if (tid < HDIM) {
        float Mg = -INFINITY;
#pragma unroll
        for (int i = 0; i < NSPLIT; i++)
            Mg = fmaxf(Mg, g_part_m[bh * NSPLIT + i]);
        float Lg = 0.f, r = 0.f;
#pragma unroll
        for (int i = 0; i < NSPLIT; i++) {
            const float mi = g_part_m[bh * NSPLIT + i];
            const float coef = (mi == -INFINITY) ? 0.f : __expf(mi - Mg);
            Lg += coef * g_part_l[bh * NSPLIT + i];
            r  += coef * g_part_o[((size_t)bh * NSPLIT + i) * HDIM + tid];
        }
        out[(size_t)bh * HDIM + tid] = r / Lg;
    }
    if (tid == 0) g_cnt[bh] = 0;   // reset for next graph replay
}

extern "C" void kernel_launch(void* const* d_in, const int* in_sizes, int n_in,
                              void* d_out, int out_size)
{
    const float* q            = (const float*)d_in[0];
    const float* k            = (const float*)d_in[1];
    const float* v            = (const float*)d_in[2];
    const float* k_cache      = (const float*)d_in[3];
    const float* v_cache      = (const float*)d_in[4];
    // d_in[5] = slot_mapping (unused: substitution at t == ctx-1 is equivalent)
    const int*   block_tables = (const int*)d_in[6];
    const int*   context_lens = (const int*)d_in[7];
    float*       out          = (float*)d_out;

    paged_attn_split_kernel<<<BATCH * HEADS * NSPLIT, THREADS>>>(
        q, k, v, k_cache, v_cache, block_tables, context_lens, out);
}

// round 8
// speedup vs baseline: 1.3296x; 1.3296x over previous
#include <cuda_runtime.h>
#include <math.h>

// Problem shape (fixed by the dataset instance)
#define BATCH 16
#define HEADS 8
#define HDIM  128
#define BSIZE 16               // tokens per cache block
#define BPS   128              // blocks per sequence
#define TMAX  (BSIZE * BPS)    // 2048 tokens
#define NSPLIT 4
#define TSPLIT (TMAX / NSPLIT)     // 512 tokens per split
#define BLKSPLIT (TSPLIT / BSIZE)  // 32 cache blocks per split
#define THREADS 256
#define NWARPS  (THREADS / 32)     // 8
#define TPW     (TSPLIT / NWARPS)  // 64 tokens per warp

// split-KV partials + completion counters (allocation-free scratch, zero-init)
__device__ float g_part_o[BATCH * HEADS * NSPLIT * HDIM];
__device__ float g_part_m[BATCH * HEADS * NSPLIT];
__device__ float g_part_l[BATCH * HEADS * NSPLIT];
__device__ unsigned int g_cnt[BATCH * HEADS];

__device__ __forceinline__ float warp_sum(float v) {
#pragma unroll
    for (int o = 16; o > 0; o >>= 1) v += __shfl_xor_sync(0xffffffffu, v, o);
    return v;
}
__device__ __forceinline__ float warp_max(float v) {
#pragma unroll
    for (int o = 16; o > 0; o >>= 1) v = fmaxf(v, __shfl_xor_sync(0xffffffffu, v, o));
    return v;
}

__global__ __launch_bounds__(THREADS)
void paged_attn_split_kernel(const float* __restrict__ q,
                             const float* __restrict__ knew,
                             const float* __restrict__ vnew,
                             const float* __restrict__ kcache,
                             const float* __restrict__ vcache,
                             const int*   __restrict__ block_tables,
                             const int*   __restrict__ context_lens,
                             float*       __restrict__ out)
{
    const float SCALE = 0.08838834764831845f;

    // Grid layout: adjacent CTAs = the 8 heads of the same (b, split) chunk.
    const int idx   = blockIdx.x;
    const int h     = idx % HEADS;
    const int bs_   = idx / HEADS;
    const int split = bs_ % NSPLIT;
    const int b     = bs_ / NSPLIT;
    const int bh    = b * HEADS + h;

    const int tid   = threadIdx.x;
    const int lane  = tid & 31;
    const int w     = tid >> 5;
    const int tbase = split * TSPLIT;

    __shared__ float s_scores[TSPLIT];
    __shared__ int   s_bt[BLKSPLIT];
    __shared__ float s_m[NWARPS];
    __shared__ float s_l[NWARPS];
    __shared__ float s_acc[NWARPS][HDIM];
    __shared__ unsigned int s_last;

    if (tid < BLKSPLIT)
        s_bt[tid] = block_tables[b * BPS + split * BLKSPLIT + tid];

    const int ctx  = context_lens[b];
    const int last = ctx - 1;

    float4 q4 = reinterpret_cast<const float4*>(q + (size_t)bh * HDIM)[lane];
    q4.x *= SCALE; q4.y *= SCALE; q4.z *= SCALE; q4.w *= SCALE;

    const float* kfresh = knew + (size_t)bh * HDIM;
    const float* vfresh = vnew + (size_t)bh * HDIM;

    __syncthreads();

    // ------------- Phase 1: scores (8-deep load batches per warp) ----------
    const int lbeg = w * TPW;
#pragma unroll 1
    for (int l0 = lbeg; l0 < lbeg + TPW; l0 += 8) {
        float4 kv[8];
#pragma unroll
        for (int i = 0; i < 8; i++) {
            const int lt = l0 + i;                 // local token in split
            const int t  = tbase + lt;             // global token
            const int blk = s_bt[lt >> 4];
            const size_t row = ((size_t)blk * BSIZE + (t & (BSIZE - 1))) * HEADS + h;
            kv[i] = (t == last)
                  ? reinterpret_cast<const float4*>(kfresh)[lane]
                  : __ldcs(reinterpret_cast<const float4*>(kcache + row * HDIM) + lane);
        }
#pragma unroll
        for (int i = 0; i < 8; i++) {
            float s = kv[i].x * q4.x + kv[i].y * q4.y + kv[i].z * q4.z + kv[i].w * q4.w;
            s = warp_sum(s);
            if (lane == i) {
                const int lt = l0 + i;
                s_scores[lt] = (tbase + lt < ctx) ? s : -INFINITY;
            }
        }
    }
    __syncwarp();

    // ------------- Phase 2: per-warp softmax (max recovered from smem) -----
    const float s0 = s_scores[lbeg + lane];
    const float s1 = s_scores[lbeg + 32 + lane];
    const float m  = warp_max(fmaxf(s0, s1));
    const float msafe = (m == -INFINITY) ? 0.0f : m;
    const float e0 = __expf(s0 - msafe);
    const float e1 = __expf(s1 - msafe);
    s_scores[lbeg + lane]      = e0;
    s_scores[lbeg + 32 + lane] = e1;
    const float l = warp_sum(e0 + e1);
    __syncwarp();

    // ------------- Phase 3: unnormalized o = sum p_t v_t -------------------
    float4 acc = make_float4(0.f, 0.f, 0.f, 0.f);
#pragma unroll 1
    for (int l0 = lbeg; l0 < lbeg + TPW; l0 += 8) {
        float4 vv[8];
        float  p[8];
#pragma unroll
        for (int i = 0; i < 8; i++) {
            const int lt = l0 + i;
            const int t  = tbase + lt;
            const int blk = s_bt[lt >> 4];
            const size_t row = ((size_t)blk * BSIZE + (t & (BSIZE - 1))) * HEADS + h;
            vv[i] = (t == last)
                  ? reinterpret_cast<const float4*>(vfresh)[lane]
                  : __ldcs(reinterpret_cast<const float4*>(vcache + row * HDIM) + lane);
            p[i]  = s_scores[lt];                   // LDS broadcast
        }
#pragma unroll
        for (int i = 0; i < 8; i++) {
            acc.x += p[i] * vv[i].x;
            acc.y += p[i] * vv[i].y;
            acc.z += p[i] * vv[i].z;
            acc.w += p[i] * vv[i].w;
        }
    }

    // ------------- cross-warp merge -> split partial ------------------------
    if (lane == 0) { s_m[w] = m; s_l[w] = l; }
    reinterpret_cast<float4*>(s_acc[w])[lane] = acc;
    __syncthreads();

    float M = -INFINITY;
#pragma unroll
    for (int ww = 0; ww < NWARPS; ww++) M = fmaxf(M, s_m[ww]);

    const int ps = bh * NSPLIT + split;
    if (tid < HDIM) {
        float r = 0.f;
#pragma unroll
        for (int ww = 0; ww < NWARPS; ww++) {
            const float coef = (s_m[ww] == -INFINITY) ? 0.f : __expf(s_m[ww] - M);
            r += coef * s_acc[ww][tid];
        }
        g_part_o[(size_t)ps * HDIM + tid] = r;
    }
    if (tid == 0) {
        float L = 0.f;
#pragma unroll
        for (int ww = 0; ww < NWARPS; ww++) {
            const float coef = (s_m[ww] == -INFINITY) ? 0.f : __expf(s_m[ww] - M);
            L += coef * s_l[ww];
        }
        g_part_m[ps] = M;
        g_part_l[ps] = L;
    }

    // ------------- last CTA per (b,h) combines (fused, no 2nd launch) ------
    __threadfence();
    __syncthreads();
    if (tid == 0)
        s_last = atomicAdd(&g_cnt[bh], 1u);
    __syncthreads();
    if (s_last != NSPLIT - 1) return;
    __threadfence();

    if (tid < HDIM) {
        float Mg = -INFINITY;
#pragma unroll
        for (int i = 0; i < NSPLIT; i++)
            Mg = fmaxf(Mg, g_part_m[bh * NSPLIT + i]);
        float Lg = 0.f, r = 0.f;
#pragma unroll
        for (int i = 0; i < NSPLIT; i++) {
            const float mi = g_part_m[bh * NSPLIT + i];
            const float coef = (mi == -INFINITY) ? 0.f : __expf(mi - Mg);
            Lg += coef * g_part_l[bh * NSPLIT + i];
            r  += coef * g_part_o[((size_t)bh * NSPLIT + i) * HDIM + tid];
        }
        out[(size_t)bh * HDIM + tid] = r / Lg;
    }
    if (tid == 0) g_cnt[bh] = 0;   // reset for next graph replay
}

extern "C" void kernel_launch(void* const* d_in, const int* in_sizes, int n_in,
                              void* d_out, int out_size)
{
    const float* q            = (const float*)d_in[0];
    const float* k            = (const float*)d_in[1];
    const float* v            = (const float*)d_in[2];
    const float* k_cache      = (const float*)d_in[3];
    const float* v_cache      = (const float*)d_in[4];
    // d_in[5] = slot_mapping (unused: substitution at t == ctx-1 is equivalent)
    const int*   block_tables = (const int*)d_in[6];
    const int*   context_lens = (const int*)d_in[7];
    float*       out          = (float*)d_out;

    paged_attn_split_kernel<<<BATCH * HEADS * NSPLIT, THREADS>>>(
        q, k, v, k_cache, v_cache, block_tables, context_lens, out);
}

// round 9
// speedup vs baseline: 1.3521x; 1.0169x over previous
#include <cuda_runtime.h>
#include <math.h>

// Problem shape (fixed by the dataset instance)
#define BATCH 16
#define HEADS 8
#define HDIM  128
#define BSIZE 16               // tokens per cache block
#define BPS   128              // blocks per sequence
#define TMAX  (BSIZE * BPS)    // 2048 tokens
#define NSPLIT 8
#define TSPLIT (TMAX / NSPLIT)     // 256 tokens per split
#define BLKSPLIT (TSPLIT / BSIZE)  // 16 cache blocks per split
#define THREADS 128
#define NWARPS  (THREADS / 32)     // 4
#define TPW     (TSPLIT / NWARPS)  // 64 tokens per warp

// split-KV partials + completion counters (allocation-free scratch, zero-init)
__device__ float g_part_o[BATCH * HEADS * NSPLIT * HDIM];
__device__ float g_part_m[BATCH * HEADS * NSPLIT];
__device__ float g_part_l[BATCH * HEADS * NSPLIT];
__device__ unsigned int g_cnt[BATCH * HEADS];

__device__ __forceinline__ float warp_sum(float v) {
#pragma unroll
    for (int o = 16; o > 0; o >>= 1) v += __shfl_xor_sync(0xffffffffu, v, o);
    return v;
}
__device__ __forceinline__ float warp_max(float v) {
#pragma unroll
    for (int o = 16; o > 0; o >>= 1) v = fmaxf(v, __shfl_xor_sync(0xffffffffu, v, o));
    return v;
}

__global__ __launch_bounds__(THREADS, 8)
void paged_attn_split_kernel(const float* __restrict__ q,
                             const float* __restrict__ knew,
                             const float* __restrict__ vnew,
                             const float* __restrict__ kcache,
                             const float* __restrict__ vcache,
                             const int*   __restrict__ block_tables,
                             const int*   __restrict__ context_lens,
                             float*       __restrict__ out)
{
    const float SCALE = 0.08838834764831845f;

    // Grid layout: adjacent CTAs = the 8 heads of the same (b, split) chunk.
    const int idx   = blockIdx.x;
    const int h     = idx % HEADS;
    const int bs_   = idx / HEADS;
    const int split = bs_ % NSPLIT;
    const int b     = bs_ / NSPLIT;
    const int bh    = b * HEADS + h;

    const int tid   = threadIdx.x;
    const int lane  = tid & 31;
    const int w     = tid >> 5;
    const int tbase = split * TSPLIT;

    __shared__ float s_scores[TSPLIT];
    __shared__ int   s_bt[BLKSPLIT];
    __shared__ float s_m[NWARPS];
    __shared__ float s_l[NWARPS];
    __shared__ float s_acc[NWARPS][HDIM];
    __shared__ unsigned int s_last;

    if (tid < BLKSPLIT)
        s_bt[tid] = block_tables[b * BPS + split * BLKSPLIT + tid];

    const int ctx  = context_lens[b];
    const int last = ctx - 1;

    float4 q4 = reinterpret_cast<const float4*>(q + (size_t)bh * HDIM)[lane];
    q4.x *= SCALE; q4.y *= SCALE; q4.z *= SCALE; q4.w *= SCALE;

    const float* kfresh = knew + (size_t)bh * HDIM;
    const float* vfresh = vnew + (size_t)bh * HDIM;

    __syncthreads();

    // ------------- Phase 1: scores (8-deep load batches per warp) ----------
    const int lbeg = w * TPW;
#pragma unroll 1
    for (int l0 = lbeg; l0 < lbeg + TPW; l0 += 8) {
        float4 kv[8];
#pragma unroll
        for (int i = 0; i < 8; i++) {
            const int lt = l0 + i;                 // local token in split
            const int t  = tbase + lt;             // global token
            const int blk = s_bt[lt >> 4];
            const size_t row = ((size_t)blk * BSIZE + (t & (BSIZE - 1))) * HEADS + h;
            kv[i] = (t == last)
                  ? reinterpret_cast<const float4*>(kfresh)[lane]
                  : __ldcs(reinterpret_cast<const float4*>(kcache + row * HDIM) + lane);
        }
#pragma unroll
        for (int i = 0; i < 8; i++) {
            float s = kv[i].x * q4.x + kv[i].y * q4.y + kv[i].z * q4.z + kv[i].w * q4.w;
            s = warp_sum(s);
            if (lane == i) {
                const int lt = l0 + i;
                s_scores[lt] = (tbase + lt < ctx) ? s : -INFINITY;
            }
        }
    }
    __syncwarp();

    // ------------- Phase 2: per-warp softmax (max recovered from smem) -----
    const float s0 = s_scores[lbeg + lane];
    const float s1 = s_scores[lbeg + 32 + lane];
    const float m  = warp_max(fmaxf(s0, s1));
    const float msafe = (m == -INFINITY) ? 0.0f : m;
    const float e0 = __expf(s0 - msafe);
    const float e1 = __expf(s1 - msafe);
    s_scores[lbeg + lane]      = e0;
    s_scores[lbeg + 32 + lane] = e1;
    const float l = warp_sum(e0 + e1);
    __syncwarp();

    // ------------- Phase 3: unnormalized o = sum p_t v_t -------------------
    float4 acc = make_float4(0.f, 0.f, 0.f, 0.f);
#pragma unroll 1
    for (int l0 = lbeg; l0 < lbeg + TPW; l0 += 8) {
        float4 vv[8];
        float  p[8];
#pragma unroll
        for (int i = 0; i < 8; i++) {
            const int lt = l0 + i;
            const int t  = tbase + lt;
            const int blk = s_bt[lt >> 4];
            const size_t row = ((size_t)blk * BSIZE + (t & (BSIZE - 1))) * HEADS + h;
            vv[i] = (t == last)
                  ? reinterpret_cast<const float4*>(vfresh)[lane]
                  : __ldcs(reinterpret_cast<const float4*>(vcache + row * HDIM) + lane);
            p[i]  = s_scores[lt];                   // LDS broadcast
        }
#pragma unroll
        for (int i = 0; i < 8; i++) {
            acc.x += p[i] * vv[i].x;
            acc.y += p[i] * vv[i].y;
            acc.z += p[i] * vv[i].z;
            acc.w += p[i] * vv[i].w;
        }
    }

    // ------------- cross-warp merge -> split partial ------------------------
    if (lane == 0) { s_m[w] = m; s_l[w] = l; }
    reinterpret_cast<float4*>(s_acc[w])[lane] = acc;
    __syncthreads();

    float M = -INFINITY;
#pragma unroll
    for (int ww = 0; ww < NWARPS; ww++) M = fmaxf(M, s_m[ww]);

    const int ps = bh * NSPLIT + split;
    if (tid < HDIM) {
        float r = 0.f;
#pragma unroll
        for (int ww = 0; ww < NWARPS; ww++) {
            const float coef = (s_m[ww] == -INFINITY) ? 0.f : __expf(s_m[ww] - M);
            r += coef * s_acc[ww][tid];
        }
        g_part_o[(size_t)ps * HDIM + tid] = r;
    }
    if (tid == 0) {
        float L = 0.f;
#pragma unroll
        for (int ww = 0; ww < NWARPS; ww++) {
            const float coef = (s_m[ww] == -INFINITY) ? 0.f : __expf(s_m[ww] - M);
            L += coef * s_l[ww];
        }
        g_part_m[ps] = M;
        g_part_l[ps] = L;
    }

    // ------------- last CTA per (b,h) combines (fused, no 2nd launch) ------
    __threadfence();
    __syncthreads();
    if (tid == 0)
        s_last = atomicAdd(&g_cnt[bh], 1u);
    __syncthreads();
    if (s_last != NSPLIT - 1) return;
    __threadfence();

    if (tid < HDIM) {
        float Mg = -INFINITY;
#pragma unroll
        for (int i = 0; i < NSPLIT; i++)
            Mg = fmaxf(Mg, g_part_m[bh * NSPLIT + i]);
        float Lg = 0.f, r = 0.f;
#pragma unroll
        for (int i = 0; i < NSPLIT; i++) {
            const float mi = g_part_m[bh * NSPLIT + i];
            const float coef = (mi == -INFINITY) ? 0.f : __expf(mi - Mg);
            Lg += coef * g_part_l[bh * NSPLIT + i];
            r  += coef * g_part_o[((size_t)bh * NSPLIT + i) * HDIM + tid];
        }
        out[(size_t)bh * HDIM + tid] = r / Lg;
    }
    if (tid == 0) g_cnt[bh] = 0;   // reset for next graph replay
}

extern "C" void kernel_launch(void* const* d_in, const int* in_sizes, int n_in,
                              void* d_out, int out_size)
{
    const float* q            = (const float*)d_in[0];
    const float* k            = (const float*)d_in[1];
    const float* v            = (const float*)d_in[2];
    const float* k_cache      = (const float*)d_in[3];
    const float* v_cache      = (const float*)d_in[4];
    // d_in[5] = slot_mapping (unused: substitution at t == ctx-1 is equivalent)
    const int*   block_tables = (const int*)d_in[6];
    const int*   context_lens = (const int*)d_in[7];
    float*       out          = (float*)d_out;

    paged_attn_split_kernel<<<BATCH * HEADS * NSPLIT, THREADS>>>(
        q, k, v, k_cache, v_cache, block_tables, context_lens, out);
}